// round 1
// baseline (speedup 1.0000x reference)
#include <cuda_runtime.h>
#include <math.h>

// Problem dims (fixed by the reference)
#define BB 2
#define TT 2048
#define CC 1024
#define NH 16
#define HD 64
#define MROWS (BB*TT)   // 4096

// Scratch (allocation-free rule: __device__ globals)
__device__ float g_qkv[(size_t)BB * TT * 3 * CC];  // [B,T,3C]
__device__ float g_y[(size_t)BB * TT * CC];        // attention output, heads merged

// ---------------------------------------------------------------------------
// SGEMM with bias: C[M,N] = A[M,K] @ B[K,N] + bias[N]
// BM=BN=128, BK=8, 256 threads, 8x8 per-thread register tile.
// M,N,K all multiples of 128/8 here; no bounds checks needed.
// ---------------------------------------------------------------------------
__global__ __launch_bounds__(256, 2)
void sgemm_bias(const float* __restrict__ A, const float* __restrict__ B,
                const float* __restrict__ bias, float* __restrict__ C,
                int M, int N, int K)
{
    const int BM = 128, BN = 128, BK = 8;
    __shared__ float As[BK][BM];
    __shared__ float Bs[BK][BN];

    const int tid  = threadIdx.x;
    const int brow = blockIdx.y, bcol = blockIdx.x;
    const int tRow = tid / 16, tCol = tid % 16;

    // load indices
    const int aRow = tid >> 1;            // 0..127
    const int aCol = (tid & 1) * 4;       // 0 or 4
    const int bRow = tid >> 5;            // 0..7
    const int bCol = (tid & 31) * 4;      // 0..124

    const float* Ag = A + (size_t)(brow * BM + aRow) * K + aCol;
    const float* Bg = B + (size_t)bRow * N + (size_t)bcol * BN + bCol;

    float acc[8][8];
    #pragma unroll
    for (int i = 0; i < 8; i++)
        #pragma unroll
        for (int j = 0; j < 8; j++) acc[i][j] = 0.f;

    for (int kt = 0; kt < K; kt += BK) {
        float4 av = *(const float4*)(Ag + kt);
        As[aCol + 0][aRow] = av.x;
        As[aCol + 1][aRow] = av.y;
        As[aCol + 2][aRow] = av.z;
        As[aCol + 3][aRow] = av.w;
        float4 bv = *(const float4*)(Bg + (size_t)kt * N);
        *(float4*)&Bs[bRow][bCol] = bv;
        __syncthreads();

        #pragma unroll
        for (int k = 0; k < BK; k++) {
            float ra[8], rb[8];
            #pragma unroll
            for (int i = 0; i < 8; i++) ra[i] = As[k][tRow * 8 + i];
            #pragma unroll
            for (int j = 0; j < 8; j++) rb[j] = Bs[k][tCol * 8 + j];
            #pragma unroll
            for (int i = 0; i < 8; i++)
                #pragma unroll
                for (int j = 0; j < 8; j++)
                    acc[i][j] += ra[i] * rb[j];
        }
        __syncthreads();
    }

    // epilogue
    const int colBase = bcol * BN + tCol * 8;
    #pragma unroll
    for (int i = 0; i < 8; i++) {
        const int r = brow * BM + tRow * 8 + i;
        float* Cr = C + (size_t)r * N + colBase;
        #pragma unroll
        for (int j = 0; j < 8; j += 4) {
            float4 o;
            o.x = acc[i][j + 0] + bias[colBase + j + 0];
            o.y = acc[i][j + 1] + bias[colBase + j + 1];
            o.z = acc[i][j + 2] + bias[colBase + j + 2];
            o.w = acc[i][j + 3] + bias[colBase + j + 3];
            *(float4*)(Cr + j) = o;
        }
    }
}

// ---------------------------------------------------------------------------
// Flash attention (fp32, online softmax).
// Grid: (T/64, NH, B). 256 threads. BQ = BKV = 64, D = 64.
// SMEM (dynamic, ~65KB):
//   Qs[d][row]  (64 x 65)  transposed
//   Ks[d][key]  (64 x 65)  transposed
//   Ps[key][row](64 x 65)  transposed probabilities
//   Vs[key][d]  (64 x 64)
//   mrow[64], lrow[64]
// Thread (trow=tid/16, tcol=tid%16) owns S[4 rows][4 keys] and O[4 rows][4 dims].
// ---------------------------------------------------------------------------
__global__ __launch_bounds__(256, 1)
void flash_attn(const float* __restrict__ qkv, float* __restrict__ y)
{
    extern __shared__ float sm[];
    float* Qs   = sm;                 // 64*65
    float* Ks   = Qs + 64 * 65;      // 64*65
    float* Ps   = Ks + 64 * 65;      // 64*65
    float* Vs   = Ps + 64 * 65;      // 64*64
    float* mrow = Vs + 64 * 64;      // 64
    float* lrow = mrow + 64;         // 64

    const int tid  = threadIdx.x;
    const int qt   = blockIdx.x;
    const int h    = blockIdx.y;
    const int b    = blockIdx.z;
    const int trow = tid / 16, tcol = tid % 16;
    const float scale = 0.125f; // 1/sqrt(64)

    const size_t strideT = 3 * CC;
    const float* qg = qkv + (size_t)b * TT * strideT + (size_t)h * HD;
    const float* kg = qg + CC;
    const float* vg = qg + 2 * CC;

    // Load Q tile transposed: Qs[d][r]
    #pragma unroll
    for (int it = 0; it < 4; it++) {
        int idx = tid + it * 256;
        int r  = idx >> 4;
        int dc = (idx & 15) << 2;
        float4 v = *(const float4*)(qg + (size_t)(qt * 64 + r) * strideT + dc);
        Qs[(dc + 0) * 65 + r] = v.x;
        Qs[(dc + 1) * 65 + r] = v.y;
        Qs[(dc + 2) * 65 + r] = v.z;
        Qs[(dc + 3) * 65 + r] = v.w;
    }
    if (tid < 64) { mrow[tid] = -INFINITY; lrow[tid] = 0.f; }

    float O[4][4];
    #pragma unroll
    for (int i = 0; i < 4; i++)
        #pragma unroll
        for (int j = 0; j < 4; j++) O[i][j] = 0.f;

    for (int j = 0; j <= qt; j++) {
        __syncthreads();   // protect Ks/Vs/Ps from previous iteration readers
        // Load K (transposed) and V tiles
        #pragma unroll
        for (int it = 0; it < 4; it++) {
            int idx = tid + it * 256;
            int r  = idx >> 4;
            int dc = (idx & 15) << 2;
            float4 kv = *(const float4*)(kg + (size_t)(j * 64 + r) * strideT + dc);
            Ks[(dc + 0) * 65 + r] = kv.x;
            Ks[(dc + 1) * 65 + r] = kv.y;
            Ks[(dc + 2) * 65 + r] = kv.z;
            Ks[(dc + 3) * 65 + r] = kv.w;
            float4 vv = *(const float4*)(vg + (size_t)(j * 64 + r) * strideT + dc);
            *(float4*)&Vs[r * 64 + dc] = vv;
        }
        __syncthreads();

        // S = Q @ K^T  (4x4 per thread)
        float s[4][4];
        #pragma unroll
        for (int i = 0; i < 4; i++)
            #pragma unroll
            for (int jj = 0; jj < 4; jj++) s[i][jj] = 0.f;
        #pragma unroll
        for (int d = 0; d < 64; d++) {
            float rq[4], rk[4];
            #pragma unroll
            for (int i = 0; i < 4; i++)  rq[i]  = Qs[d * 65 + trow * 4 + i];
            #pragma unroll
            for (int jj = 0; jj < 4; jj++) rk[jj] = Ks[d * 65 + tcol * 4 + jj];
            #pragma unroll
            for (int i = 0; i < 4; i++)
                #pragma unroll
                for (int jj = 0; jj < 4; jj++)
                    s[i][jj] += rq[i] * rk[jj];
        }

        // scale + causal mask (only the diagonal tile needs masking)
        if (j == qt) {
            #pragma unroll
            for (int i = 0; i < 4; i++)
                #pragma unroll
                for (int jj = 0; jj < 4; jj++) {
                    int qr = trow * 4 + i, kr = tcol * 4 + jj;
                    s[i][jj] = (kr <= qr) ? s[i][jj] * scale : -INFINITY;
                }
        } else {
            #pragma unroll
            for (int i = 0; i < 4; i++)
                #pragma unroll
                for (int jj = 0; jj < 4; jj++) s[i][jj] *= scale;
        }

        // Online softmax. 16 threads (same trow, tcol 0..15) share each row group;
        // they occupy a contiguous 16-lane half-warp, so shfl_xor 1,2,4,8 reduces
        // within the group.
        float a_i[4], mnew_i[4], psum_i[4], p[4][4];
        #pragma unroll
        for (int i = 0; i < 4; i++) {
            float mx = fmaxf(fmaxf(s[i][0], s[i][1]), fmaxf(s[i][2], s[i][3]));
            #pragma unroll
            for (int off = 1; off < 16; off <<= 1)
                mx = fmaxf(mx, __shfl_xor_sync(0xffffffffu, mx, off));
            const int row = trow * 4 + i;
            float mold = mrow[row];          // read before any lane writes
            float mnew = fmaxf(mold, mx);
            a_i[i]    = __expf(mold - mnew); // 0 when mold = -inf
            mnew_i[i] = mnew;
            float ps = 0.f;
            #pragma unroll
            for (int jj = 0; jj < 4; jj++) {
                p[i][jj] = __expf(s[i][jj] - mnew);
                ps += p[i][jj];
            }
            #pragma unroll
            for (int off = 1; off < 16; off <<= 1)
                ps += __shfl_xor_sync(0xffffffffu, ps, off);
            psum_i[i] = ps;
        }
        __syncwarp();  // all reads of mrow/lrow done before the writes below
        if (tcol == 0) {
            #pragma unroll
            for (int i = 0; i < 4; i++) {
                const int row = trow * 4 + i;
                mrow[row] = mnew_i[i];
                lrow[row] = lrow[row] * a_i[i] + psum_i[i];
            }
        }
        // write P transposed: Ps[key][row]
        #pragma unroll
        for (int i = 0; i < 4; i++)
            #pragma unroll
            for (int jj = 0; jj < 4; jj++)
                Ps[(tcol * 4 + jj) * 65 + trow * 4 + i] = p[i][jj];
        __syncthreads();

        // rescale O, then O += P @ V (4 rows x 4 dims per thread)
        #pragma unroll
        for (int i = 0; i < 4; i++)
            #pragma unroll
            for (int jd = 0; jd < 4; jd++) O[i][jd] *= a_i[i];
        #pragma unroll
        for (int key = 0; key < 64; key++) {
            float pr[4], vr[4];
            #pragma unroll
            for (int i = 0; i < 4; i++)  pr[i]  = Ps[key * 65 + trow * 4 + i];
            #pragma unroll
            for (int jd = 0; jd < 4; jd++) vr[jd] = Vs[key * 64 + tcol * 4 + jd];
            #pragma unroll
            for (int i = 0; i < 4; i++)
                #pragma unroll
                for (int jd = 0; jd < 4; jd++)
                    O[i][jd] += pr[i] * vr[jd];
        }
    }

    __syncthreads();  // lrow writes visible
    #pragma unroll
    for (int i = 0; i < 4; i++) {
        const int row = trow * 4 + i;
        const float linv = 1.f / lrow[row];
        float4 o;
        o.x = O[i][0] * linv;
        o.y = O[i][1] * linv;
        o.z = O[i][2] * linv;
        o.w = O[i][3] * linv;
        *(float4*)(y + (size_t)((size_t)b * TT + qt * 64 + row) * CC
                     + (size_t)h * HD + tcol * 4) = o;
    }
}

// ---------------------------------------------------------------------------
extern "C" void kernel_launch(void* const* d_in, const int* in_sizes, int n_in,
                              void* d_out, int out_size)
{
    const float* x      = (const float*)d_in[0];
    const float* w_attn = (const float*)d_in[1];
    const float* b_attn = (const float*)d_in[2];
    const float* w_proj = (const float*)d_in[3];
    const float* b_proj = (const float*)d_in[4];
    float* out = (float*)d_out;

    float* qkv = nullptr;
    float* yb  = nullptr;
    cudaGetSymbolAddress((void**)&qkv, g_qkv);
    cudaGetSymbolAddress((void**)&yb,  g_y);

    const int flashSmem = (3 * 64 * 65 + 64 * 64 + 2 * 64) * (int)sizeof(float); // 66816
    cudaFuncSetAttribute(flash_attn, cudaFuncAttributeMaxDynamicSharedMemorySize, flashSmem);

    // 1) qkv = x @ w_attn + b_attn        [4096,3072]
    sgemm_bias<<<dim3(3 * CC / 128, MROWS / 128), 256>>>(
        x, w_attn, b_attn, qkv, MROWS, 3 * CC, CC);

    // 2) flash attention -> g_y           [4096,1024]
    flash_attn<<<dim3(TT / 64, NH, BB), 256, flashSmem>>>(qkv, yb);

    // 3) out = y @ w_proj + b_proj        [4096,1024]
    sgemm_bias<<<dim3(CC / 128, MROWS / 128), 256>>>(
        yb, w_proj, b_proj, out, MROWS, CC, CC);
}

// round 4
// speedup vs baseline: 1.0214x; 1.0214x over previous
#include <cuda_runtime.h>
#include <math.h>
#include <stdint.h>

// Problem dims (fixed by the reference)
#define BB 2
#define TT 2048
#define CC 1024
#define NH 16
#define HD 64
#define MROWS (BB*TT)   // 4096

// Scratch (allocation-free rule: __device__ globals)
__device__ float g_qkv[(size_t)BB * TT * 3 * CC];  // [B,T,3C]
__device__ float g_y[(size_t)MROWS * CC];          // attention output (tf32-rounded)
__device__ float g_x[(size_t)MROWS * CC];          // tf32-rounded x
__device__ float g_wa[(size_t)CC * 3 * CC];        // tf32-rounded w_attn
__device__ float g_wp[(size_t)CC * CC];            // tf32-rounded w_proj

// ---------------------------------------------------------------------------
__device__ __forceinline__ float to_tf32(float f) {
    uint32_t r;
    asm("cvt.rna.tf32.f32 %0, %1;" : "=r"(r) : "f"(f));
    return __uint_as_float(r);
}

// mma.sync m16n8k8 tf32 (sm_80+ path; works on sm_100 plain target)
__device__ __forceinline__ void mma_tf32(float c[4], const uint32_t a[4], const uint32_t b[2]) {
    asm volatile(
        "mma.sync.aligned.m16n8k8.row.col.f32.tf32.tf32.f32 "
        "{%0,%1,%2,%3}, {%4,%5,%6,%7}, {%8,%9}, {%0,%1,%2,%3};"
        : "+f"(c[0]), "+f"(c[1]), "+f"(c[2]), "+f"(c[3])
        : "r"(a[0]), "r"(a[1]), "r"(a[2]), "r"(a[3]), "r"(b[0]), "r"(b[1]));
}

// ---------------------------------------------------------------------------
// elementwise tf32 rounding (rna)
// ---------------------------------------------------------------------------
__global__ void round_tf32(const float* __restrict__ in, float* __restrict__ out, int n4) {
    int i = blockIdx.x * blockDim.x + threadIdx.x;
    int stride = gridDim.x * blockDim.x;
    for (; i < n4; i += stride) {
        float4 v = ((const float4*)in)[i];
        v.x = to_tf32(v.x); v.y = to_tf32(v.y);
        v.z = to_tf32(v.z); v.w = to_tf32(v.w);
        ((float4*)out)[i] = v;
    }
}

// ---------------------------------------------------------------------------
// tf32 tensor-core GEMM via mma.sync: C[M,N] = A[M,K] @ B[K,N] + bias[N]
// CTA tile 128x128, BK=32, 256 threads (8 warps, 4x2), warp tile 32x64.
// SMEM holds A/B pre-packed in m16n8k8 fragment order:
//   A: [buf][kstep(4)][m16(8)][lane(32)][areg(4)]   (4096 floats / buf)
//   B: [buf][kstep(4)][n8(16)][lane(32)][breg(2)]   (4096 floats / buf)
// Fragment mapping (PTX ISA m16n8k8 tf32, row.col):
//   A: a0=(r,c) a1=(r+8,c) a2=(r,c+4) a3=(r+8,c+4); r=lane>>2, c=lane&3
//   B: b0=(k=lane&3, n=lane>>2) b1=(k+4, n)
//   C: c0=(r, 2c) c1=(r, 2c+1) c2=(r+8, 2c) c3=(r+8, 2c+1)
// ---------------------------------------------------------------------------
__global__ __launch_bounds__(256, 2)
void gemm_mma(const float* __restrict__ A, const float* __restrict__ B,
              const float* __restrict__ bias, float* __restrict__ C,
              int M, int N, int K)
{
    extern __shared__ float sm[];
    // float offsets
    //   A buf0: 0,  A buf1: 4096,  B buf0: 8192,  B buf1: 12288
    const int tid  = threadIdx.x;
    const int lane = tid & 31;
    const int wid  = tid >> 5;
    const int wm   = wid >> 1;       // 0..3  (M blocks of 32)
    const int wn   = wid & 1;        // 0..1  (N blocks of 64)
    const int brow = blockIdx.y, bcol = blockIdx.x;

    // --- loader index precompute (A: 4 float4/thread, B: 4 float4/thread) ---
    // A: id = tid + i*256 -> row = id>>3 (0..127), kc4 = (id&7)*4
    // B: id = tid + i*256 -> k = id>>5 (0..31),  n4 = (id&31)*4
    float4 ra[4], rb[4];

    const float* Ag = A + (size_t)(brow * 128) * K;
    const float* Bg = B + (size_t)bcol * 128;

    auto ldg_tile = [&](int kt) {
        #pragma unroll
        for (int i = 0; i < 4; i++) {
            int id  = tid + i * 256;
            int row = id >> 3, kc4 = (id & 7) << 2;
            ra[i] = *(const float4*)(Ag + (size_t)row * K + kt * 32 + kc4);
        }
        #pragma unroll
        for (int i = 0; i < 4; i++) {
            int id = tid + i * 256;
            int k  = id >> 5, n4 = (id & 31) << 2;
            rb[i] = *(const float4*)(Bg + (size_t)(kt * 32 + k) * N + n4);
        }
    };

    auto sts_tile = [&](int buf) {
        float* sA = sm + buf * 4096;
        float* sB = sm + 8192 + buf * 4096;
        #pragma unroll
        for (int i = 0; i < 4; i++) {
            int id  = tid + i * 256;
            int row = id >> 3, kc4 = (id & 7) << 2;
            int ks  = kc4 >> 3;
            int khi = (kc4 >> 2) & 1;
            int m16 = row >> 4, rlo = row & 7, rhi = (row >> 3) & 1;
            int reg = rhi + 2 * khi;
            const float* f = (const float*)&ra[i];
            #pragma unroll
            for (int e = 0; e < 4; e++) {
                int ln = rlo * 4 + e;
                sA[((ks * 8 + m16) * 32 + ln) * 4 + reg] = f[e];
            }
        }
        #pragma unroll
        for (int i = 0; i < 4; i++) {
            int id = tid + i * 256;
            int k  = id >> 5, n4 = (id & 31) << 2;
            int ks = k >> 3, klo = k & 3, khi = (k >> 2) & 1;
            const float* f = (const float*)&rb[i];
            #pragma unroll
            for (int e = 0; e < 4; e++) {
                int n  = n4 + e;
                int n8 = n >> 3, nn = n & 7;
                int ln = nn * 4 + klo;
                sB[((ks * 16 + n8) * 32 + ln) * 2 + khi] = f[e];
            }
        }
    };

    float acc[2][8][4];
    #pragma unroll
    for (int i = 0; i < 2; i++)
        #pragma unroll
        for (int j = 0; j < 8; j++)
            #pragma unroll
            for (int e = 0; e < 4; e++) acc[i][j][e] = 0.f;

    const int NT = K / 32;

    ldg_tile(0);
    sts_tile(0);
    ldg_tile(1);
    __syncthreads();

    for (int kt = 0; kt < NT; kt++) {
        const int cur = kt & 1;
        if (kt + 1 < NT) sts_tile(cur ^ 1);
        if (kt + 2 < NT) ldg_tile(kt + 2);

        const float* sA = sm + cur * 4096;
        const float* sB = sm + 8192 + cur * 4096;
        #pragma unroll
        for (int ks = 0; ks < 4; ks++) {
            uint32_t a[2][4], b[8][2];
            #pragma unroll
            for (int i = 0; i < 2; i++) {
                float4 v = *(const float4*)(sA + ((ks * 8 + wm * 2 + i) * 32 + lane) * 4);
                a[i][0] = __float_as_uint(v.x); a[i][1] = __float_as_uint(v.y);
                a[i][2] = __float_as_uint(v.z); a[i][3] = __float_as_uint(v.w);
            }
            #pragma unroll
            for (int j = 0; j < 8; j++) {
                float2 v = *(const float2*)(sB + ((ks * 16 + wn * 8 + j) * 32 + lane) * 2);
                b[j][0] = __float_as_uint(v.x); b[j][1] = __float_as_uint(v.y);
            }
            #pragma unroll
            for (int i = 0; i < 2; i++)
                #pragma unroll
                for (int j = 0; j < 8; j++)
                    mma_tf32(acc[i][j], a[i], b[j]);
        }
        __syncthreads();
    }

    // epilogue
    #pragma unroll
    for (int i = 0; i < 2; i++) {
        const int gm0 = brow * 128 + wm * 32 + i * 16 + (lane >> 2);
        #pragma unroll
        for (int j = 0; j < 8; j++) {
            const int gn = bcol * 128 + wn * 64 + j * 8 + (lane & 3) * 2;
            const float b0 = bias[gn], b1 = bias[gn + 1];
            float2 o0 = make_float2(acc[i][j][0] + b0, acc[i][j][1] + b1);
            float2 o1 = make_float2(acc[i][j][2] + b0, acc[i][j][3] + b1);
            *(float2*)(C + (size_t)gm0 * N + gn)       = o0;
            *(float2*)(C + (size_t)(gm0 + 8) * N + gn) = o1;
        }
    }
}

// ---------------------------------------------------------------------------
// Flash attention (fp32, online softmax) — R1-proven version; stores y rounded
// to tf32 so GEMM2 can consume it directly.
// ---------------------------------------------------------------------------
__global__ __launch_bounds__(256, 1)
void flash_attn(const float* __restrict__ qkv, float* __restrict__ y)
{
    extern __shared__ float sm[];
    float* Qs   = sm;                 // 64*65
    float* Ks   = Qs + 64 * 65;      // 64*65
    float* Ps   = Ks + 64 * 65;      // 64*65
    float* Vs   = Ps + 64 * 65;      // 64*64
    float* mrow = Vs + 64 * 64;      // 64
    float* lrow = mrow + 64;         // 64

    const int tid  = threadIdx.x;
    const int qt   = blockIdx.x;
    const int h    = blockIdx.y;
    const int b    = blockIdx.z;
    const int trow = tid / 16, tcol = tid % 16;
    const float scale = 0.125f; // 1/sqrt(64)

    const size_t strideT = 3 * CC;
    const float* qg = qkv + (size_t)b * TT * strideT + (size_t)h * HD;
    const float* kg = qg + CC;
    const float* vg = qg + 2 * CC;

    #pragma unroll
    for (int it = 0; it < 4; it++) {
        int idx = tid + it * 256;
        int r  = idx >> 4;
        int dc = (idx & 15) << 2;
        float4 v = *(const float4*)(qg + (size_t)(qt * 64 + r) * strideT + dc);
        Qs[(dc + 0) * 65 + r] = v.x;
        Qs[(dc + 1) * 65 + r] = v.y;
        Qs[(dc + 2) * 65 + r] = v.z;
        Qs[(dc + 3) * 65 + r] = v.w;
    }
    if (tid < 64) { mrow[tid] = -INFINITY; lrow[tid] = 0.f; }

    float O[4][4];
    #pragma unroll
    for (int i = 0; i < 4; i++)
        #pragma unroll
        for (int j = 0; j < 4; j++) O[i][j] = 0.f;

    for (int j = 0; j <= qt; j++) {
        __syncthreads();
        #pragma unroll
        for (int it = 0; it < 4; it++) {
            int idx = tid + it * 256;
            int r  = idx >> 4;
            int dc = (idx & 15) << 2;
            float4 kv = *(const float4*)(kg + (size_t)(j * 64 + r) * strideT + dc);
            Ks[(dc + 0) * 65 + r] = kv.x;
            Ks[(dc + 1) * 65 + r] = kv.y;
            Ks[(dc + 2) * 65 + r] = kv.z;
            Ks[(dc + 3) * 65 + r] = kv.w;
            float4 vv = *(const float4*)(vg + (size_t)(j * 64 + r) * strideT + dc);
            *(float4*)&Vs[r * 64 + dc] = vv;
        }
        __syncthreads();

        float s[4][4];
        #pragma unroll
        for (int i = 0; i < 4; i++)
            #pragma unroll
            for (int jj = 0; jj < 4; jj++) s[i][jj] = 0.f;
        #pragma unroll
        for (int d = 0; d < 64; d++) {
            float rq[4], rk[4];
            #pragma unroll
            for (int i = 0; i < 4; i++)  rq[i]  = Qs[d * 65 + trow * 4 + i];
            #pragma unroll
            for (int jj = 0; jj < 4; jj++) rk[jj] = Ks[d * 65 + tcol * 4 + jj];
            #pragma unroll
            for (int i = 0; i < 4; i++)
                #pragma unroll
                for (int jj = 0; jj < 4; jj++)
                    s[i][jj] += rq[i] * rk[jj];
        }

        if (j == qt) {
            #pragma unroll
            for (int i = 0; i < 4; i++)
                #pragma unroll
                for (int jj = 0; jj < 4; jj++) {
                    int qr = trow * 4 + i, kr = tcol * 4 + jj;
                    s[i][jj] = (kr <= qr) ? s[i][jj] * scale : -INFINITY;
                }
        } else {
            #pragma unroll
            for (int i = 0; i < 4; i++)
                #pragma unroll
                for (int jj = 0; jj < 4; jj++) s[i][jj] *= scale;
        }

        float a_i[4], mnew_i[4], psum_i[4], p[4][4];
        #pragma unroll
        for (int i = 0; i < 4; i++) {
            float mx = fmaxf(fmaxf(s[i][0], s[i][1]), fmaxf(s[i][2], s[i][3]));
            #pragma unroll
            for (int off = 1; off < 16; off <<= 1)
                mx = fmaxf(mx, __shfl_xor_sync(0xffffffffu, mx, off));
            const int row = trow * 4 + i;
            float mold = mrow[row];
            float mnew = fmaxf(mold, mx);
            a_i[i]    = __expf(mold - mnew);
            mnew_i[i] = mnew;
            float ps = 0.f;
            #pragma unroll
            for (int jj = 0; jj < 4; jj++) {
                p[i][jj] = __expf(s[i][jj] - mnew);
                ps += p[i][jj];
            }
            #pragma unroll
            for (int off = 1; off < 16; off <<= 1)
                ps += __shfl_xor_sync(0xffffffffu, ps, off);
            psum_i[i] = ps;
        }
        __syncwarp();
        if (tcol == 0) {
            #pragma unroll
            for (int i = 0; i < 4; i++) {
                const int row = trow * 4 + i;
                mrow[row] = mnew_i[i];
                lrow[row] = lrow[row] * a_i[i] + psum_i[i];
            }
        }
        #pragma unroll
        for (int i = 0; i < 4; i++)
            #pragma unroll
            for (int jj = 0; jj < 4; jj++)
                Ps[(tcol * 4 + jj) * 65 + trow * 4 + i] = p[i][jj];
        __syncthreads();

        #pragma unroll
        for (int i = 0; i < 4; i++)
            #pragma unroll
            for (int jd = 0; jd < 4; jd++) O[i][jd] *= a_i[i];
        #pragma unroll
        for (int key = 0; key < 64; key++) {
            float pr[4], vr[4];
            #pragma unroll
            for (int i = 0; i < 4; i++)  pr[i]  = Ps[key * 65 + trow * 4 + i];
            #pragma unroll
            for (int jd = 0; jd < 4; jd++) vr[jd] = Vs[key * 64 + tcol * 4 + jd];
            #pragma unroll
            for (int i = 0; i < 4; i++)
                #pragma unroll
                for (int jd = 0; jd < 4; jd++)
                    O[i][jd] += pr[i] * vr[jd];
        }
    }

    __syncthreads();
    #pragma unroll
    for (int i = 0; i < 4; i++) {
        const int row = trow * 4 + i;
        const float linv = 1.f / lrow[row];
        float4 o;
        o.x = to_tf32(O[i][0] * linv);
        o.y = to_tf32(O[i][1] * linv);
        o.z = to_tf32(O[i][2] * linv);
        o.w = to_tf32(O[i][3] * linv);
        *(float4*)(y + (size_t)((size_t)b * TT + qt * 64 + row) * CC
                     + (size_t)h * HD + tcol * 4) = o;
    }
}

// ---------------------------------------------------------------------------
extern "C" void kernel_launch(void* const* d_in, const int* in_sizes, int n_in,
                              void* d_out, int out_size)
{
    const float* x      = (const float*)d_in[0];
    const float* w_attn = (const float*)d_in[1];
    const float* b_attn = (const float*)d_in[2];
    const float* w_proj = (const float*)d_in[3];
    const float* b_proj = (const float*)d_in[4];
    float* out = (float*)d_out;

    float *qkv, *yb, *xr, *war, *wpr;
    cudaGetSymbolAddress((void**)&qkv, g_qkv);
    cudaGetSymbolAddress((void**)&yb,  g_y);
    cudaGetSymbolAddress((void**)&xr,  g_x);
    cudaGetSymbolAddress((void**)&war, g_wa);
    cudaGetSymbolAddress((void**)&wpr, g_wp);

    const int gemmSmem = 16384 * (int)sizeof(float); // 64 KB
    cudaFuncSetAttribute(gemm_mma, cudaFuncAttributeMaxDynamicSharedMemorySize, gemmSmem);
    const int flashSmem = (3 * 64 * 65 + 64 * 64 + 2 * 64) * (int)sizeof(float); // 66816
    cudaFuncSetAttribute(flash_attn, cudaFuncAttributeMaxDynamicSharedMemorySize, flashSmem);

    // tf32(rna) pre-rounding of GEMM operands
    round_tf32<<<592, 256>>>(x,      xr,  MROWS * CC / 4);
    round_tf32<<<592, 256>>>(w_attn, war, CC * 3 * CC / 4);
    round_tf32<<<592, 256>>>(w_proj, wpr, CC * CC / 4);

    // 1) qkv = x @ w_attn + b_attn        [4096,3072]  (mma.sync tf32)
    gemm_mma<<<dim3(3 * CC / 128, MROWS / 128), 256, gemmSmem>>>(
        xr, war, b_attn, qkv, MROWS, 3 * CC, CC);

    // 2) flash attention -> g_y (tf32-rounded)
    flash_attn<<<dim3(TT / 64, NH, BB), 256, flashSmem>>>(qkv, yb);

    // 3) out = y @ w_proj + b_proj        [4096,1024]  (mma.sync tf32)
    gemm_mma<<<dim3(CC / 128, MROWS / 128), 256, gemmSmem>>>(
        yb, wpr, b_proj, out, MROWS, CC, CC);
}

// round 5
// speedup vs baseline: 1.7321x; 1.6957x over previous
#include <cuda_runtime.h>
#include <math.h>
#include <stdint.h>

// Problem dims (fixed by the reference)
#define BB 2
#define TT 2048
#define CC 1024
#define NH 16
#define HD 64
#define MROWS (BB*TT)   // 4096

// Scratch (allocation-free rule: __device__ globals)
__device__ float g_qkv[(size_t)BB * TT * 3 * CC];  // [B,T,3C]
__device__ float g_y[(size_t)MROWS * CC];          // attention output (tf32-rounded)
__device__ float g_x[(size_t)MROWS * CC];          // tf32-rounded x
__device__ float g_wa[(size_t)CC * 3 * CC];        // tf32-rounded w_attn
__device__ float g_wp[(size_t)CC * CC];            // tf32-rounded w_proj

// ---------------------------------------------------------------------------
__device__ __forceinline__ float to_tf32(float f) {
    uint32_t r;
    asm("cvt.rna.tf32.f32 %0, %1;" : "=r"(r) : "f"(f));
    return __uint_as_float(r);
}

// mma.sync m16n8k8 tf32 (sm_80+ path; supported on plain sm_100 target)
__device__ __forceinline__ void mma_tf32(float c[4], const uint32_t a[4], const uint32_t b[2]) {
    asm volatile(
        "mma.sync.aligned.m16n8k8.row.col.f32.tf32.tf32.f32 "
        "{%0,%1,%2,%3}, {%4,%5,%6,%7}, {%8,%9}, {%0,%1,%2,%3};"
        : "+f"(c[0]), "+f"(c[1]), "+f"(c[2]), "+f"(c[3])
        : "r"(a[0]), "r"(a[1]), "r"(a[2]), "r"(a[3]), "r"(b[0]), "r"(b[1]));
}

__device__ __forceinline__ uint32_t smem_u32(const void* p) {
    uint32_t a;
    asm("{ .reg .u64 t; cvta.to.shared.u64 t, %1; cvt.u32.u64 %0, t; }" : "=r"(a) : "l"(p));
    return a;
}
__device__ __forceinline__ void cp_async16(uint32_t dst, const void* src) {
    asm volatile("cp.async.cg.shared.global [%0], [%1], 16;" :: "r"(dst), "l"(src) : "memory");
}
__device__ __forceinline__ void cp_commit() {
    asm volatile("cp.async.commit_group;" ::: "memory");
}
template <int N>
__device__ __forceinline__ void cp_wait() {
    asm volatile("cp.async.wait_group %0;" :: "n"(N) : "memory");
}

// ---------------------------------------------------------------------------
// elementwise tf32 rounding (rna)
// ---------------------------------------------------------------------------
__global__ void round_tf32(const float* __restrict__ in, float* __restrict__ out, int n4) {
    int i = blockIdx.x * blockDim.x + threadIdx.x;
    int stride = gridDim.x * blockDim.x;
    for (; i < n4; i += stride) {
        float4 v = ((const float4*)in)[i];
        v.x = to_tf32(v.x); v.y = to_tf32(v.y);
        v.z = to_tf32(v.z); v.w = to_tf32(v.w);
        ((float4*)out)[i] = v;
    }
}

// ---------------------------------------------------------------------------
// tf32 mma.sync GEMM v2: C[M,N] = A[M,K] @ B[K,N] + bias[N]
// CTA 128x128, BK=32, 128 threads (4 warps, 2x2), warp tile 64x64.
// cp.async 3-stage pipeline, natural row-major SMEM with bank-tuned padding:
//   sA [128][36]  (A frag LDS banks 4r+c -> conflict-free)
//   sB [32][136]  (B frag banks 8*klo + 8j + u -> conflict-free)
// Stage = 18432 + 17408 = 35840 B; 3 stages = 107520 B; 2 CTAs/SM.
// ---------------------------------------------------------------------------
#define SA_LD 36
#define SB_LD 136
#define STAGE_F 8960           // floats per stage (35840 B)
#define SA_F 4608              // floats in sA (18432 B)

__global__ __launch_bounds__(128, 2)
void gemm_mma(const float* __restrict__ A, const float* __restrict__ B,
              const float* __restrict__ bias, float* __restrict__ C,
              int M, int N, int K)
{
    extern __shared__ float sm[];
    const uint32_t sbase = smem_u32(sm);
    const int tid  = threadIdx.x;
    const int lane = tid & 31;
    const int wid  = tid >> 5;
    const int wm   = wid & 1;        // 0..1 (64-row block)
    const int wn   = wid >> 1;       // 0..1 (64-col block)
    const int brow = blockIdx.y, bcol = blockIdx.x;

    const float* Ag = A + (size_t)(brow * 128) * K;
    const float* Bg = B + (size_t)bcol * 128;

    const int NT = K / 32;

    auto issue_stage = [&](int kt, int s) {
        const uint32_t stage_b = (uint32_t)s * (STAGE_F * 4);
        #pragma unroll
        for (int i = 0; i < 8; i++) {
            int id  = tid + i * 128;
            int row = id >> 3, c4 = (id & 7) << 2;
            uint32_t dst = sbase + stage_b + (uint32_t)(row * SA_LD + c4) * 4u;
            cp_async16(dst, Ag + (size_t)row * K + kt * 32 + c4);
        }
        #pragma unroll
        for (int i = 0; i < 8; i++) {
            int id = tid + i * 128;
            int k  = id >> 5, n4 = (id & 31) << 2;
            uint32_t dst = sbase + stage_b + (uint32_t)(SA_F + k * SB_LD + n4) * 4u;
            cp_async16(dst, Bg + (size_t)(kt * 32 + k) * N + n4);
        }
        cp_commit();
    };

    float acc[4][8][4];
    #pragma unroll
    for (int i = 0; i < 4; i++)
        #pragma unroll
        for (int j = 0; j < 8; j++)
            #pragma unroll
            for (int e = 0; e < 4; e++) acc[i][j][e] = 0.f;

    issue_stage(0, 0);
    issue_stage(1, 1);

    const int r4 = lane >> 2;   // 0..7
    const int c4 = lane & 3;    // 0..3

    for (int kt = 0; kt < NT; kt++) {
        if (kt + 2 < NT) cp_wait<1>(); else cp_wait<0>();
        __syncthreads();
        if (kt + 2 < NT) issue_stage(kt + 2, (kt + 2) % 3);

        const float* sA = sm + (kt % 3) * STAGE_F;
        const float* sB = sA + SA_F;

        #pragma unroll
        for (int ks = 0; ks < 4; ks++) {
            uint32_t a[4][4], b[8][2];
            #pragma unroll
            for (int i = 0; i < 4; i++) {
                const float* p = sA + (wm * 64 + i * 16 + r4) * SA_LD + ks * 8 + c4;
                a[i][0] = __float_as_uint(p[0]);
                a[i][1] = __float_as_uint(p[8 * SA_LD]);
                a[i][2] = __float_as_uint(p[4]);
                a[i][3] = __float_as_uint(p[8 * SA_LD + 4]);
            }
            #pragma unroll
            for (int j = 0; j < 8; j++) {
                const float* p = sB + (ks * 8 + c4) * SB_LD + wn * 64 + j * 8 + r4;
                b[j][0] = __float_as_uint(p[0]);
                b[j][1] = __float_as_uint(p[4 * SB_LD]);
            }
            #pragma unroll
            for (int i = 0; i < 4; i++)
                #pragma unroll
                for (int j = 0; j < 8; j++)
                    mma_tf32(acc[i][j], a[i], b[j]);
        }
        __syncthreads();
    }

    // epilogue: row = brow*128 + wm*64 + i*16 + r4 (+8), col = bcol*128 + wn*64 + j*8 + c4*2
    #pragma unroll
    for (int i = 0; i < 4; i++) {
        const int gm0 = brow * 128 + wm * 64 + i * 16 + r4;
        #pragma unroll
        for (int j = 0; j < 8; j++) {
            const int gn = bcol * 128 + wn * 64 + j * 8 + c4 * 2;
            const float b0 = bias[gn], b1 = bias[gn + 1];
            float2 o0 = make_float2(acc[i][j][0] + b0, acc[i][j][1] + b1);
            float2 o1 = make_float2(acc[i][j][2] + b0, acc[i][j][3] + b1);
            *(float2*)(C + (size_t)gm0 * N + gn)       = o0;
            *(float2*)(C + (size_t)(gm0 + 8) * N + gn) = o1;
        }
    }
}

// ---------------------------------------------------------------------------
// Flash attention (fp32, online softmax) — R1-proven version; stores y rounded
// to tf32 so GEMM2 can consume it directly.
// ---------------------------------------------------------------------------
__global__ __launch_bounds__(256, 1)
void flash_attn(const float* __restrict__ qkv, float* __restrict__ y)
{
    extern __shared__ float sm[];
    float* Qs   = sm;                 // 64*65
    float* Ks   = Qs + 64 * 65;      // 64*65
    float* Ps   = Ks + 64 * 65;      // 64*65
    float* Vs   = Ps + 64 * 65;      // 64*64
    float* mrow = Vs + 64 * 64;      // 64
    float* lrow = mrow + 64;         // 64

    const int tid  = threadIdx.x;
    const int qt   = blockIdx.x;
    const int h    = blockIdx.y;
    const int b    = blockIdx.z;
    const int trow = tid / 16, tcol = tid % 16;
    const float scale = 0.125f; // 1/sqrt(64)

    const size_t strideT = 3 * CC;
    const float* qg = qkv + (size_t)b * TT * strideT + (size_t)h * HD;
    const float* kg = qg + CC;
    const float* vg = qg + 2 * CC;

    #pragma unroll
    for (int it = 0; it < 4; it++) {
        int idx = tid + it * 256;
        int r  = idx >> 4;
        int dc = (idx & 15) << 2;
        float4 v = *(const float4*)(qg + (size_t)(qt * 64 + r) * strideT + dc);
        Qs[(dc + 0) * 65 + r] = v.x;
        Qs[(dc + 1) * 65 + r] = v.y;
        Qs[(dc + 2) * 65 + r] = v.z;
        Qs[(dc + 3) * 65 + r] = v.w;
    }
    if (tid < 64) { mrow[tid] = -INFINITY; lrow[tid] = 0.f; }

    float O[4][4];
    #pragma unroll
    for (int i = 0; i < 4; i++)
        #pragma unroll
        for (int j = 0; j < 4; j++) O[i][j] = 0.f;

    for (int j = 0; j <= qt; j++) {
        __syncthreads();
        #pragma unroll
        for (int it = 0; it < 4; it++) {
            int idx = tid + it * 256;
            int r  = idx >> 4;
            int dc = (idx & 15) << 2;
            float4 kv = *(const float4*)(kg + (size_t)(j * 64 + r) * strideT + dc);
            Ks[(dc + 0) * 65 + r] = kv.x;
            Ks[(dc + 1) * 65 + r] = kv.y;
            Ks[(dc + 2) * 65 + r] = kv.z;
            Ks[(dc + 3) * 65 + r] = kv.w;
            float4 vv = *(const float4*)(vg + (size_t)(j * 64 + r) * strideT + dc);
            *(float4*)&Vs[r * 64 + dc] = vv;
        }
        __syncthreads();

        float s[4][4];
        #pragma unroll
        for (int i = 0; i < 4; i++)
            #pragma unroll
            for (int jj = 0; jj < 4; jj++) s[i][jj] = 0.f;
        #pragma unroll
        for (int d = 0; d < 64; d++) {
            float rq[4], rk[4];
            #pragma unroll
            for (int i = 0; i < 4; i++)  rq[i]  = Qs[d * 65 + trow * 4 + i];
            #pragma unroll
            for (int jj = 0; jj < 4; jj++) rk[jj] = Ks[d * 65 + tcol * 4 + jj];
            #pragma unroll
            for (int i = 0; i < 4; i++)
                #pragma unroll
                for (int jj = 0; jj < 4; jj++)
                    s[i][jj] += rq[i] * rk[jj];
        }

        if (j == qt) {
            #pragma unroll
            for (int i = 0; i < 4; i++)
                #pragma unroll
                for (int jj = 0; jj < 4; jj++) {
                    int qr = trow * 4 + i, kr = tcol * 4 + jj;
                    s[i][jj] = (kr <= qr) ? s[i][jj] * scale : -INFINITY;
                }
        } else {
            #pragma unroll
            for (int i = 0; i < 4; i++)
                #pragma unroll
                for (int jj = 0; jj < 4; jj++) s[i][jj] *= scale;
        }

        float a_i[4], mnew_i[4], psum_i[4], p[4][4];
        #pragma unroll
        for (int i = 0; i < 4; i++) {
            float mx = fmaxf(fmaxf(s[i][0], s[i][1]), fmaxf(s[i][2], s[i][3]));
            #pragma unroll
            for (int off = 1; off < 16; off <<= 1)
                mx = fmaxf(mx, __shfl_xor_sync(0xffffffffu, mx, off));
            const int row = trow * 4 + i;
            float mold = mrow[row];
            float mnew = fmaxf(mold, mx);
            a_i[i]    = __expf(mold - mnew);
            mnew_i[i] = mnew;
            float ps = 0.f;
            #pragma unroll
            for (int jj = 0; jj < 4; jj++) {
                p[i][jj] = __expf(s[i][jj] - mnew);
                ps += p[i][jj];
            }
            #pragma unroll
            for (int off = 1; off < 16; off <<= 1)
                ps += __shfl_xor_sync(0xffffffffu, ps, off);
            psum_i[i] = ps;
        }
        __syncwarp();
        if (tcol == 0) {
            #pragma unroll
            for (int i = 0; i < 4; i++) {
                const int row = trow * 4 + i;
                mrow[row] = mnew_i[i];
                lrow[row] = lrow[row] * a_i[i] + psum_i[i];
            }
        }
        #pragma unroll
        for (int i = 0; i < 4; i++)
            #pragma unroll
            for (int jj = 0; jj < 4; jj++)
                Ps[(tcol * 4 + jj) * 65 + trow * 4 + i] = p[i][jj];
        __syncthreads();

        #pragma unroll
        for (int i = 0; i < 4; i++)
            #pragma unroll
            for (int jd = 0; jd < 4; jd++) O[i][jd] *= a_i[i];
        #pragma unroll
        for (int key = 0; key < 64; key++) {
            float pr[4], vr[4];
            #pragma unroll
            for (int i = 0; i < 4; i++)  pr[i]  = Ps[key * 65 + trow * 4 + i];
            #pragma unroll
            for (int jd = 0; jd < 4; jd++) vr[jd] = Vs[key * 64 + tcol * 4 + jd];
            #pragma unroll
            for (int i = 0; i < 4; i++)
                #pragma unroll
                for (int jd = 0; jd < 4; jd++)
                    O[i][jd] += pr[i] * vr[jd];
        }
    }

    __syncthreads();
    #pragma unroll
    for (int i = 0; i < 4; i++) {
        const int row = trow * 4 + i;
        const float linv = 1.f / lrow[row];
        float4 o;
        o.x = to_tf32(O[i][0] * linv);
        o.y = to_tf32(O[i][1] * linv);
        o.z = to_tf32(O[i][2] * linv);
        o.w = to_tf32(O[i][3] * linv);
        *(float4*)(y + (size_t)((size_t)b * TT + qt * 64 + row) * CC
                     + (size_t)h * HD + tcol * 4) = o;
    }
}

// ---------------------------------------------------------------------------
extern "C" void kernel_launch(void* const* d_in, const int* in_sizes, int n_in,
                              void* d_out, int out_size)
{
    const float* x      = (const float*)d_in[0];
    const float* w_attn = (const float*)d_in[1];
    const float* b_attn = (const float*)d_in[2];
    const float* w_proj = (const float*)d_in[3];
    const float* b_proj = (const float*)d_in[4];
    float* out = (float*)d_out;

    float *qkv, *yb, *xr, *war, *wpr;
    cudaGetSymbolAddress((void**)&qkv, g_qkv);
    cudaGetSymbolAddress((void**)&yb,  g_y);
    cudaGetSymbolAddress((void**)&xr,  g_x);
    cudaGetSymbolAddress((void**)&war, g_wa);
    cudaGetSymbolAddress((void**)&wpr, g_wp);

    const int gemmSmem = 3 * STAGE_F * (int)sizeof(float); // 107520
    cudaFuncSetAttribute(gemm_mma, cudaFuncAttributeMaxDynamicSharedMemorySize, gemmSmem);
    const int flashSmem = (3 * 64 * 65 + 64 * 64 + 2 * 64) * (int)sizeof(float); // 66816
    cudaFuncSetAttribute(flash_attn, cudaFuncAttributeMaxDynamicSharedMemorySize, flashSmem);

    // tf32(rna) pre-rounding of GEMM operands
    round_tf32<<<592, 256>>>(x,      xr,  MROWS * CC / 4);
    round_tf32<<<592, 256>>>(w_attn, war, CC * 3 * CC / 4);
    round_tf32<<<592, 256>>>(w_proj, wpr, CC * CC / 4);

    // 1) qkv = x @ w_attn + b_attn        [4096,3072]  (mma.sync tf32)
    gemm_mma<<<dim3(3 * CC / 128, MROWS / 128), 128, gemmSmem>>>(
        xr, war, b_attn, qkv, MROWS, 3 * CC, CC);

    // 2) flash attention -> g_y (tf32-rounded)
    flash_attn<<<dim3(TT / 64, NH, BB), 256, flashSmem>>>(qkv, yb);

    // 3) out = y @ w_proj + b_proj        [4096,1024]  (mma.sync tf32)
    gemm_mma<<<dim3(CC / 128, MROWS / 128), 128, gemmSmem>>>(
        yb, wpr, b_proj, out, MROWS, CC, CC);
}

// round 6
// speedup vs baseline: 3.6588x; 2.1124x over previous
#include <cuda_runtime.h>
#include <math.h>
#include <stdint.h>

// Problem dims (fixed by the reference)
#define BB 2
#define TT 2048
#define CC 1024
#define NH 16
#define HD 64
#define MROWS (BB*TT)   // 4096

// Scratch (allocation-free rule: __device__ globals)
__device__ float g_qkv[(size_t)BB * TT * 3 * CC];  // [B,T,3C] (tf32-rounded)
__device__ float g_y[(size_t)MROWS * CC];          // attention output (tf32-rounded)
__device__ float g_x[(size_t)MROWS * CC];          // tf32-rounded x
__device__ float g_wa[(size_t)CC * 3 * CC];        // tf32-rounded w_attn
__device__ float g_wp[(size_t)CC * CC];            // tf32-rounded w_proj

// ---------------------------------------------------------------------------
__device__ __forceinline__ float to_tf32(float f) {
    uint32_t r;
    asm("cvt.rna.tf32.f32 %0, %1;" : "=r"(r) : "f"(f));
    return __uint_as_float(r);
}

// mma.sync m16n8k8 tf32 (sm_80+ path; supported on plain sm_100 target)
__device__ __forceinline__ void mma_tf32(float c[4], const uint32_t a[4], const uint32_t b[2]) {
    asm volatile(
        "mma.sync.aligned.m16n8k8.row.col.f32.tf32.tf32.f32 "
        "{%0,%1,%2,%3}, {%4,%5,%6,%7}, {%8,%9}, {%0,%1,%2,%3};"
        : "+f"(c[0]), "+f"(c[1]), "+f"(c[2]), "+f"(c[3])
        : "r"(a[0]), "r"(a[1]), "r"(a[2]), "r"(a[3]), "r"(b[0]), "r"(b[1]));
}

__device__ __forceinline__ uint32_t smem_u32(const void* p) {
    uint32_t a;
    asm("{ .reg .u64 t; cvta.to.shared.u64 t, %1; cvt.u32.u64 %0, t; }" : "=r"(a) : "l"(p));
    return a;
}
__device__ __forceinline__ void cp_async16(uint32_t dst, const void* src) {
    asm volatile("cp.async.cg.shared.global [%0], [%1], 16;" :: "r"(dst), "l"(src) : "memory");
}
__device__ __forceinline__ void cp_commit() {
    asm volatile("cp.async.commit_group;" ::: "memory");
}
template <int N>
__device__ __forceinline__ void cp_wait() {
    asm volatile("cp.async.wait_group %0;" :: "n"(N) : "memory");
}

// ---------------------------------------------------------------------------
// elementwise tf32 rounding (rna)
// ---------------------------------------------------------------------------
__global__ void round_tf32(const float* __restrict__ in, float* __restrict__ out, int n4) {
    int i = blockIdx.x * blockDim.x + threadIdx.x;
    int stride = gridDim.x * blockDim.x;
    for (; i < n4; i += stride) {
        float4 v = ((const float4*)in)[i];
        v.x = to_tf32(v.x); v.y = to_tf32(v.y);
        v.z = to_tf32(v.z); v.w = to_tf32(v.w);
        ((float4*)out)[i] = v;
    }
}

// ---------------------------------------------------------------------------
// tf32 mma.sync GEMM: C[M,N] = A[M,K] @ B[K,N] + bias[N]
// CTA 128x128, BK=32, 128 threads (4 warps, 2x2), warp tile 64x64.
// cp.async 3-stage pipeline; sA [128][36], sB [32][136] (conflict-free frags).
// round_out != 0 -> store outputs tf32(rna)-rounded (for downstream mma use).
// ---------------------------------------------------------------------------
#define SA_LD 36
#define SB_LD 136
#define STAGE_F 8960           // floats per stage (35840 B)
#define SA_F 4608              // floats in sA (18432 B)

__global__ __launch_bounds__(128, 2)
void gemm_mma(const float* __restrict__ A, const float* __restrict__ B,
              const float* __restrict__ bias, float* __restrict__ C,
              int M, int N, int K, int round_out)
{
    extern __shared__ float sm[];
    const uint32_t sbase = smem_u32(sm);
    const int tid  = threadIdx.x;
    const int lane = tid & 31;
    const int wid  = tid >> 5;
    const int wm   = wid & 1;
    const int wn   = wid >> 1;
    const int brow = blockIdx.y, bcol = blockIdx.x;

    const float* Ag = A + (size_t)(brow * 128) * K;
    const float* Bg = B + (size_t)bcol * 128;

    const int NT = K / 32;

    auto issue_stage = [&](int kt, int s) {
        const uint32_t stage_b = (uint32_t)s * (STAGE_F * 4);
        #pragma unroll
        for (int i = 0; i < 8; i++) {
            int id  = tid + i * 128;
            int row = id >> 3, c4 = (id & 7) << 2;
            uint32_t dst = sbase + stage_b + (uint32_t)(row * SA_LD + c4) * 4u;
            cp_async16(dst, Ag + (size_t)row * K + kt * 32 + c4);
        }
        #pragma unroll
        for (int i = 0; i < 8; i++) {
            int id = tid + i * 128;
            int k  = id >> 5, n4 = (id & 31) << 2;
            uint32_t dst = sbase + stage_b + (uint32_t)(SA_F + k * SB_LD + n4) * 4u;
            cp_async16(dst, Bg + (size_t)(kt * 32 + k) * N + n4);
        }
        cp_commit();
    };

    float acc[4][8][4];
    #pragma unroll
    for (int i = 0; i < 4; i++)
        #pragma unroll
        for (int j = 0; j < 8; j++)
            #pragma unroll
            for (int e = 0; e < 4; e++) acc[i][j][e] = 0.f;

    issue_stage(0, 0);
    issue_stage(1, 1);

    const int r4 = lane >> 2;
    const int c4 = lane & 3;

    for (int kt = 0; kt < NT; kt++) {
        if (kt + 2 < NT) cp_wait<1>(); else cp_wait<0>();
        __syncthreads();
        if (kt + 2 < NT) issue_stage(kt + 2, (kt + 2) % 3);

        const float* sA = sm + (kt % 3) * STAGE_F;
        const float* sB = sA + SA_F;

        #pragma unroll
        for (int ks = 0; ks < 4; ks++) {
            uint32_t a[4][4], b[8][2];
            #pragma unroll
            for (int i = 0; i < 4; i++) {
                const float* p = sA + (wm * 64 + i * 16 + r4) * SA_LD + ks * 8 + c4;
                a[i][0] = __float_as_uint(p[0]);
                a[i][1] = __float_as_uint(p[8 * SA_LD]);
                a[i][2] = __float_as_uint(p[4]);
                a[i][3] = __float_as_uint(p[8 * SA_LD + 4]);
            }
            #pragma unroll
            for (int j = 0; j < 8; j++) {
                const float* p = sB + (ks * 8 + c4) * SB_LD + wn * 64 + j * 8 + r4;
                b[j][0] = __float_as_uint(p[0]);
                b[j][1] = __float_as_uint(p[4 * SB_LD]);
            }
            #pragma unroll
            for (int i = 0; i < 4; i++)
                #pragma unroll
                for (int j = 0; j < 8; j++)
                    mma_tf32(acc[i][j], a[i], b[j]);
        }
        __syncthreads();
    }

    #pragma unroll
    for (int i = 0; i < 4; i++) {
        const int gm0 = brow * 128 + wm * 64 + i * 16 + r4;
        #pragma unroll
        for (int j = 0; j < 8; j++) {
            const int gn = bcol * 128 + wn * 64 + j * 8 + c4 * 2;
            const float b0 = bias[gn], b1 = bias[gn + 1];
            float v00 = acc[i][j][0] + b0, v01 = acc[i][j][1] + b1;
            float v10 = acc[i][j][2] + b0, v11 = acc[i][j][3] + b1;
            if (round_out) {
                v00 = to_tf32(v00); v01 = to_tf32(v01);
                v10 = to_tf32(v10); v11 = to_tf32(v11);
            }
            *(float2*)(C + (size_t)gm0 * N + gn)       = make_float2(v00, v01);
            *(float2*)(C + (size_t)(gm0 + 8) * N + gn) = make_float2(v10, v11);
        }
    }
}

// ---------------------------------------------------------------------------
// Flash attention v2: mma.sync tf32, online softmax in fragment layout.
// Grid (32, NH, BB), 128 threads (4 warps), BQ=64 (warp m16), BKV=64, D=64.
// SMEM (floats): Q[64][68] @0, P[64][68] @4352, K double [64][68] @8704,
//                V double [64][72] @17408; total 26624 f = 106496 B; 2 CTA/SM.
// qkv entries are tf32(rna)-rounded by the QKV GEMM epilogue, so fragment
// loads are raw bit patterns; P is rounded at its smem write.
// ---------------------------------------------------------------------------
#define FQ_OFF 0
#define FP_OFF 4352
#define FK_OFF 8704
#define FV_OFF 17408
#define FLASH_SMEM_B (26624 * 4)

__global__ __launch_bounds__(128, 2)
void flash_mma(const float* __restrict__ qkv, float* __restrict__ y)
{
    extern __shared__ float sm[];
    const uint32_t sbase = smem_u32(sm);
    const int tid  = threadIdx.x;
    const int lane = tid & 31;
    const int w    = tid >> 5;
    const int r4   = lane >> 2;
    const int c4   = lane & 3;
    const int qt   = gridDim.x - 1 - blockIdx.x;   // big tiles first
    const int h    = blockIdx.y;
    const int b    = blockIdx.z;

    const size_t strideT = 3 * CC;
    const float* qg = qkv + (size_t)b * TT * strideT + (size_t)h * HD
                          + (size_t)(qt * 64) * strideT;
    const float* kg = qkv + (size_t)b * TT * strideT + (size_t)h * HD + CC;
    const float* vg = kg + CC;

    auto issue_q = [&]() {
        #pragma unroll
        for (int i = 0; i < 8; i++) {
            int id = tid + i * 128;
            int row = id >> 4, cc = (id & 15) << 2;
            cp_async16(sbase + (uint32_t)(FQ_OFF + row * 68 + cc) * 4u,
                       qg + (size_t)row * strideT + cc);
        }
    };
    auto issue_kv = [&](int j, int buf) {
        const float* kgj = kg + (size_t)(j * 64) * strideT;
        const float* vgj = vg + (size_t)(j * 64) * strideT;
        #pragma unroll
        for (int i = 0; i < 8; i++) {
            int id = tid + i * 128;
            int row = id >> 4, cc = (id & 15) << 2;
            cp_async16(sbase + (uint32_t)(FK_OFF + buf * 4352 + row * 68 + cc) * 4u,
                       kgj + (size_t)row * strideT + cc);
        }
        #pragma unroll
        for (int i = 0; i < 8; i++) {
            int id = tid + i * 128;
            int row = id >> 4, cc = (id & 15) << 2;
            cp_async16(sbase + (uint32_t)(FV_OFF + buf * 4608 + row * 72 + cc) * 4u,
                       vgj + (size_t)row * strideT + cc);
        }
    };

    issue_q();
    issue_kv(0, 0);
    cp_commit();

    uint32_t qa[8][4];
    float o[8][4];
    #pragma unroll
    for (int j2 = 0; j2 < 8; j2++)
        #pragma unroll
        for (int e = 0; e < 4; e++) o[j2][e] = 0.f;
    float m0 = -INFINITY, m1 = -INFINITY, l0 = 0.f, l1 = 0.f;

    for (int j = 0; j <= qt; j++) {
        cp_wait<0>();
        __syncthreads();
        if (j < qt) { issue_kv(j + 1, (j + 1) & 1); cp_commit(); }

        if (j == 0) {
            // Preload Q fragments once, scale folded in (0.125 = 2^-3, exact).
            #pragma unroll
            for (int ks = 0; ks < 8; ks++) {
                const float* p = sm + FQ_OFF + (w * 16 + r4) * 68 + ks * 8 + c4;
                qa[ks][0] = __float_as_uint(p[0]        * 0.125f);
                qa[ks][1] = __float_as_uint(p[8 * 68]   * 0.125f);
                qa[ks][2] = __float_as_uint(p[4]        * 0.125f);
                qa[ks][3] = __float_as_uint(p[8 * 68 + 4] * 0.125f);
            }
        }

        const float* Ksm = sm + FK_OFF + (j & 1) * 4352;
        const float* Vsm = sm + FV_OFF + (j & 1) * 4608;

        // S = Q @ K^T  (warp: m16 x n64)
        float c[8][4];
        #pragma unroll
        for (int j2 = 0; j2 < 8; j2++)
            #pragma unroll
            for (int e = 0; e < 4; e++) c[j2][e] = 0.f;

        #pragma unroll
        for (int ks = 0; ks < 8; ks++) {
            uint32_t bk[8][2];
            #pragma unroll
            for (int j2 = 0; j2 < 8; j2++) {
                const float* p = Ksm + (j2 * 8 + r4) * 68 + ks * 8 + c4;
                bk[j2][0] = __float_as_uint(p[0]);
                bk[j2][1] = __float_as_uint(p[4]);
            }
            #pragma unroll
            for (int j2 = 0; j2 < 8; j2++)
                mma_tf32(c[j2], qa[ks], bk[j2]);
        }

        // causal mask (diagonal tile only)
        if (j == qt) {
            const int row0 = w * 16 + r4, row1 = row0 + 8;
            #pragma unroll
            for (int j2 = 0; j2 < 8; j2++) {
                const int col = j2 * 8 + 2 * c4;
                if (col     > row0) c[j2][0] = -INFINITY;
                if (col + 1 > row0) c[j2][1] = -INFINITY;
                if (col     > row1) c[j2][2] = -INFINITY;
                if (col + 1 > row1) c[j2][3] = -INFINITY;
            }
        }

        // online softmax (rows r4 / r4+8, quad-reduced)
        float mx0 = -INFINITY, mx1 = -INFINITY;
        #pragma unroll
        for (int j2 = 0; j2 < 8; j2++) {
            mx0 = fmaxf(mx0, fmaxf(c[j2][0], c[j2][1]));
            mx1 = fmaxf(mx1, fmaxf(c[j2][2], c[j2][3]));
        }
        mx0 = fmaxf(mx0, __shfl_xor_sync(0xffffffffu, mx0, 1));
        mx0 = fmaxf(mx0, __shfl_xor_sync(0xffffffffu, mx0, 2));
        mx1 = fmaxf(mx1, __shfl_xor_sync(0xffffffffu, mx1, 1));
        mx1 = fmaxf(mx1, __shfl_xor_sync(0xffffffffu, mx1, 2));

        const float mn0 = fmaxf(m0, mx0), mn1 = fmaxf(m1, mx1);
        const float al0 = __expf(m0 - mn0), al1 = __expf(m1 - mn1);
        m0 = mn0; m1 = mn1;

        float ps0 = 0.f, ps1 = 0.f;
        #pragma unroll
        for (int j2 = 0; j2 < 8; j2++) {
            c[j2][0] = __expf(c[j2][0] - mn0);
            c[j2][1] = __expf(c[j2][1] - mn0);
            c[j2][2] = __expf(c[j2][2] - mn1);
            c[j2][3] = __expf(c[j2][3] - mn1);
            ps0 += c[j2][0] + c[j2][1];
            ps1 += c[j2][2] + c[j2][3];
        }
        ps0 += __shfl_xor_sync(0xffffffffu, ps0, 1);
        ps0 += __shfl_xor_sync(0xffffffffu, ps0, 2);
        ps1 += __shfl_xor_sync(0xffffffffu, ps1, 1);
        ps1 += __shfl_xor_sync(0xffffffffu, ps1, 2);
        l0 = l0 * al0 + ps0;
        l1 = l1 * al1 + ps1;

        #pragma unroll
        for (int j2 = 0; j2 < 8; j2++) {
            o[j2][0] *= al0; o[j2][1] *= al0;
            o[j2][2] *= al1; o[j2][3] *= al1;
        }

        // write P (tf32-rounded) to per-warp smem strip, reload as A-frags
        #pragma unroll
        for (int j2 = 0; j2 < 8; j2++) {
            *(float2*)(sm + FP_OFF + (w * 16 + r4) * 68 + j2 * 8 + 2 * c4)
                = make_float2(to_tf32(c[j2][0]), to_tf32(c[j2][1]));
            *(float2*)(sm + FP_OFF + (w * 16 + r4 + 8) * 68 + j2 * 8 + 2 * c4)
                = make_float2(to_tf32(c[j2][2]), to_tf32(c[j2][3]));
        }
        __syncwarp();

        // O += P @ V
        #pragma unroll
        for (int ks = 0; ks < 8; ks++) {
            uint32_t pa[4];
            {
                const float* p = sm + FP_OFF + (w * 16 + r4) * 68 + ks * 8 + c4;
                pa[0] = __float_as_uint(p[0]);
                pa[1] = __float_as_uint(p[8 * 68]);
                pa[2] = __float_as_uint(p[4]);
                pa[3] = __float_as_uint(p[8 * 68 + 4]);
            }
            uint32_t bv[8][2];
            #pragma unroll
            for (int j2 = 0; j2 < 8; j2++) {
                const float* p = Vsm + (ks * 8 + c4) * 72 + j2 * 8 + r4;
                bv[j2][0] = __float_as_uint(p[0]);
                bv[j2][1] = __float_as_uint(p[4 * 72]);
            }
            #pragma unroll
            for (int j2 = 0; j2 < 8; j2++)
                mma_tf32(o[j2], pa, bv[j2]);
        }
        __syncwarp();
    }

    // final store (tf32-rounded for the proj GEMM)
    const float il0 = 1.f / l0, il1 = 1.f / l1;
    const int gr0 = qt * 64 + w * 16 + r4;
    #pragma unroll
    for (int j2 = 0; j2 < 8; j2++) {
        const int col = h * HD + j2 * 8 + 2 * c4;
        *(float2*)(y + (size_t)((size_t)b * TT + gr0) * CC + col)
            = make_float2(to_tf32(o[j2][0] * il0), to_tf32(o[j2][1] * il0));
        *(float2*)(y + (size_t)((size_t)b * TT + gr0 + 8) * CC + col)
            = make_float2(to_tf32(o[j2][2] * il1), to_tf32(o[j2][3] * il1));
    }
}

// ---------------------------------------------------------------------------
extern "C" void kernel_launch(void* const* d_in, const int* in_sizes, int n_in,
                              void* d_out, int out_size)
{
    const float* x      = (const float*)d_in[0];
    const float* w_attn = (const float*)d_in[1];
    const float* b_attn = (const float*)d_in[2];
    const float* w_proj = (const float*)d_in[3];
    const float* b_proj = (const float*)d_in[4];
    float* out = (float*)d_out;

    float *qkv, *yb, *xr, *war, *wpr;
    cudaGetSymbolAddress((void**)&qkv, g_qkv);
    cudaGetSymbolAddress((void**)&yb,  g_y);
    cudaGetSymbolAddress((void**)&xr,  g_x);
    cudaGetSymbolAddress((void**)&war, g_wa);
    cudaGetSymbolAddress((void**)&wpr, g_wp);

    const int gemmSmem = 3 * STAGE_F * (int)sizeof(float); // 107520
    cudaFuncSetAttribute(gemm_mma, cudaFuncAttributeMaxDynamicSharedMemorySize, gemmSmem);
    cudaFuncSetAttribute(flash_mma, cudaFuncAttributeMaxDynamicSharedMemorySize, FLASH_SMEM_B);

    // tf32(rna) pre-rounding of GEMM operands
    round_tf32<<<592, 256>>>(x,      xr,  MROWS * CC / 4);
    round_tf32<<<592, 256>>>(w_attn, war, CC * 3 * CC / 4);
    round_tf32<<<592, 256>>>(w_proj, wpr, CC * CC / 4);

    // 1) qkv = x @ w_attn + b_attn  (tf32 mma; output tf32-rounded for flash)
    gemm_mma<<<dim3(3 * CC / 128, MROWS / 128), 128, gemmSmem>>>(
        xr, war, b_attn, qkv, MROWS, 3 * CC, CC, 1);

    // 2) flash attention (mma.sync tf32) -> g_y (tf32-rounded)
    flash_mma<<<dim3(TT / 64, NH, BB), 128, FLASH_SMEM_B>>>(qkv, yb);

    // 3) out = y @ w_proj + b_proj  (tf32 mma; fp32 output)
    gemm_mma<<<dim3(CC / 128, MROWS / 128), 128, gemmSmem>>>(
        yb, wpr, b_proj, out, MROWS, CC, CC, 0);
}